// round 2
// baseline (speedup 1.0000x reference)
#include <cuda_runtime.h>

#define DIM 128
#define NC  4
#define LPE 8   // lanes per edge

// Folded weights: M[j][d] = sum_c Wc[c][j] * w_rel[c][d]
__device__ float g_M[NC * DIM];

__global__ void fold_weights_kernel(const float* __restrict__ w_rel,
                                    const float* __restrict__ w_cls) {
    int t = blockIdx.x * blockDim.x + threadIdx.x;
    if (t < NC * DIM) {
        int j = t / DIM, d = t % DIM;
        float s = 0.f;
#pragma unroll
        for (int c = 0; c < NC; ++c)
            s += w_cls[c * NC + j] * w_rel[c * DIM + d];
        g_M[j * DIM + d] = s;
    }
}

__global__ __launch_bounds__(256) void edge_kernel(
    const float* __restrict__ rna,
    const float* __restrict__ prot,
    const int* __restrict__ ridx,
    const int* __restrict__ pidx,
    float* __restrict__ out,
    int E)
{
    const int tid = blockIdx.x * blockDim.x + threadIdx.x;
    const int g   = threadIdx.x & (LPE - 1);        // lane within 8-lane group
    const int e   = tid >> 3;                        // edge id

    // Folded weight slices in registers: lane g owns float4s at
    // float4-index (8*k + g), k = 0..3  (i.e. d = 32k + 4g .. +3)
    const float4* Mv = reinterpret_cast<const float4*>(g_M);
    float4 M0[4], M1[4], M2[4], M3[4];
#pragma unroll
    for (int k = 0; k < 4; ++k) {
        int off = 8 * k + g;
        M0[k] = Mv[0 * 32 + off];
        M1[k] = Mv[1 * 32 + off];
        M2[k] = Mv[2 * 32 + off];
        M3[k] = Mv[3 * 32 + off];
    }

    // Clamp so all lanes stay active for the warp shuffles; predicate the store.
    const bool valid = (e < E);
    const int ee = valid ? e : (E - 1);

    const int ri = ridx[ee];
    const int pi = pidx[ee];
    const float4* rb = reinterpret_cast<const float4*>(rna)  + (long long)ri * (DIM / 4);
    const float4* pb = reinterpret_cast<const float4*>(prot) + (long long)pi * (DIM / 4);

    float a0 = 0.f, a1 = 0.f, a2 = 0.f, a3 = 0.f;
#pragma unroll
    for (int k = 0; k < 4; ++k) {
        int off = 8 * k + g;
        float4 r = rb[off];
        float4 p = pb[off];
        float4 rp;
        rp.x = r.x * p.x; rp.y = r.y * p.y; rp.z = r.z * p.z; rp.w = r.w * p.w;
        a0 += rp.x * M0[k].x + rp.y * M0[k].y + rp.z * M0[k].z + rp.w * M0[k].w;
        a1 += rp.x * M1[k].x + rp.y * M1[k].y + rp.z * M1[k].z + rp.w * M1[k].w;
        a2 += rp.x * M2[k].x + rp.y * M2[k].y + rp.z * M2[k].z + rp.w * M2[k].w;
        a3 += rp.x * M3[k].x + rp.y * M3[k].y + rp.z * M3[k].z + rp.w * M3[k].w;
    }

    // Butterfly reduction within each 8-lane group (xor 4,2,1 stays in-group).
#pragma unroll
    for (int off = 4; off >= 1; off >>= 1) {
        a0 += __shfl_xor_sync(0xffffffffu, a0, off);
        a1 += __shfl_xor_sync(0xffffffffu, a1, off);
        a2 += __shfl_xor_sync(0xffffffffu, a2, off);
        a3 += __shfl_xor_sync(0xffffffffu, a3, off);
    }

    if (valid && g == 0) {
        float4 o;
        o.x = fmaxf(a0, 0.f);
        o.y = fmaxf(a1, 0.f);
        o.z = fmaxf(a2, 0.f);
        o.w = fmaxf(a3, 0.f);
        reinterpret_cast<float4*>(out)[e] = o;
    }
}

extern "C" void kernel_launch(void* const* d_in, const int* in_sizes, int n_in,
                              void* d_out, int out_size) {
    const float* rna  = (const float*)d_in[0];   // [20000,128] f32
    const float* prot = (const float*)d_in[1];   // [5000,128]  f32
    const int*   ridx = (const int*)d_in[2];     // [E] int32 (JAX x64 off)
    const int*   pidx = (const int*)d_in[3];     // [E] int32
    const float* wrel = (const float*)d_in[4];   // [4,128] f32
    const float* wcls = (const float*)d_in[5];   // [4,4]   f32
    float*       out  = (float*)d_out;           // [E,4]   f32

    const int E = in_sizes[2];

    fold_weights_kernel<<<1, NC * DIM>>>(wrel, wcls);

    const int threads = 256;
    const long long total = (long long)E * LPE;
    const int blocks = (int)((total + threads - 1) / threads);
    edge_kernel<<<blocks, threads>>>(rna, prot, ridx, pidx, out, E);
}

// round 3
// speedup vs baseline: 1.4435x; 1.4435x over previous
#include <cuda_runtime.h>

#define DIM 128
#define NC  4
#define LPE 8   // lanes per edge-group

// Folded weights: M[j][d] = sum_c Wc[c][j] * w_rel[c][d]
__device__ float g_M[NC * DIM];

__global__ void fold_weights_kernel(const float* __restrict__ w_rel,
                                    const float* __restrict__ w_cls) {
    int t = blockIdx.x * blockDim.x + threadIdx.x;
    if (t < NC * DIM) {
        int j = t / DIM, d = t % DIM;
        float s = 0.f;
#pragma unroll
        for (int c = 0; c < NC; ++c)
            s += w_cls[c * NC + j] * w_rel[c * DIM + d];
        g_M[j * DIM + d] = s;
    }
}

// Streaming load: these gathers are ~guaranteed L1 misses (12.8MB tables,
// random index). no_allocate skips the L1 fill/allocate stage.
__device__ __forceinline__ float4 ldg_na(const float4* p) {
    float4 v;
    asm("ld.global.L1::no_allocate.v4.f32 {%0,%1,%2,%3}, [%4];"
        : "=f"(v.x), "=f"(v.y), "=f"(v.z), "=f"(v.w) : "l"(p));
    return v;
}

// Per-8-lane-group dot products for one edge, accumulators a[4] (classes).
__device__ __forceinline__ void edge_accum(const float4* __restrict__ rb,
                                           const float4* __restrict__ pb,
                                           const float4 M0[4], const float4 M1[4],
                                           const float4 M2[4], const float4 M3[4],
                                           int g, float a[4]) {
#pragma unroll
    for (int k = 0; k < 4; ++k) {
        int off = 8 * k + g;
        float4 r = ldg_na(rb + off);
        float4 p = ldg_na(pb + off);
        float4 rp;
        rp.x = r.x * p.x; rp.y = r.y * p.y; rp.z = r.z * p.z; rp.w = r.w * p.w;
        a[0] += rp.x * M0[k].x + rp.y * M0[k].y + rp.z * M0[k].z + rp.w * M0[k].w;
        a[1] += rp.x * M1[k].x + rp.y * M1[k].y + rp.z * M1[k].z + rp.w * M1[k].w;
        a[2] += rp.x * M2[k].x + rp.y * M2[k].y + rp.z * M2[k].z + rp.w * M2[k].w;
        a[3] += rp.x * M3[k].x + rp.y * M3[k].y + rp.z * M3[k].z + rp.w * M3[k].w;
    }
}

// Accumulator-splitting butterfly: 4 class-sums over 8 lanes in 4 SHFLs.
// Returns this lane's class value; lane g<4 owns class c = ((g&1)<<1)|((g>>1)&1).
__device__ __forceinline__ float reduce_split(const float a[4], int g) {
    // xor 1: even lanes keep classes {0,1}, odd keep {2,3}
    float x = (g & 1) ? a[0] : a[2];
    float y = (g & 1) ? a[1] : a[3];
    float rx = __shfl_xor_sync(0xffffffffu, x, 1);
    float ry = __shfl_xor_sync(0xffffffffu, y, 1);
    float A = ((g & 1) ? a[2] : a[0]) + rx;
    float B = ((g & 1) ? a[3] : a[1]) + ry;
    // xor 2: bit1=0 keeps first class of its pair, bit1=1 keeps second
    float z = (g & 2) ? A : B;
    float rz = __shfl_xor_sync(0xffffffffu, z, 2);
    float S = ((g & 2) ? B : A) + rz;
    // xor 4: fold the two 4-lane halves
    S += __shfl_xor_sync(0xffffffffu, S, 4);
    return S;
}

__global__ __launch_bounds__(256) void edge_kernel(
    const float* __restrict__ rna,
    const float* __restrict__ prot,
    const int* __restrict__ ridx,
    const int* __restrict__ pidx,
    float* __restrict__ out,
    int E)
{
    const int tid = blockIdx.x * blockDim.x + threadIdx.x;
    const int g   = threadIdx.x & (LPE - 1);
    const int q   = tid >> 3;          // group id: handles edges 2q, 2q+1
    const int e0  = 2 * q;
    const int e1  = 2 * q + 1;

    // Folded weights in registers (lane g owns d = 32k + 4g .. +3)
    const float4* Mv = reinterpret_cast<const float4*>(g_M);
    float4 M0[4], M1[4], M2[4], M3[4];
#pragma unroll
    for (int k = 0; k < 4; ++k) {
        int off = 8 * k + g;
        M0[k] = Mv[0 * 32 + off];
        M1[k] = Mv[1 * 32 + off];
        M2[k] = Mv[2 * 32 + off];
        M3[k] = Mv[3 * 32 + off];
    }

    const bool v0 = (e0 < E);
    const bool v1 = (e1 < E);
    const int ee0 = v0 ? e0 : 0;
    const int ee1 = v1 ? e1 : 0;

    const int ri0 = ridx[ee0], ri1 = ridx[ee1];
    const int pi0 = pidx[ee0], pi1 = pidx[ee1];
    const float4* rv = reinterpret_cast<const float4*>(rna);
    const float4* pv = reinterpret_cast<const float4*>(prot);
    const float4* rb0 = rv + (long long)ri0 * (DIM / 4);
    const float4* pb0 = pv + (long long)pi0 * (DIM / 4);
    const float4* rb1 = rv + (long long)ri1 * (DIM / 4);
    const float4* pb1 = pv + (long long)pi1 * (DIM / 4);

    float a0[4] = {0.f, 0.f, 0.f, 0.f};
    float a1[4] = {0.f, 0.f, 0.f, 0.f};
    edge_accum(rb0, pb0, M0, M1, M2, M3, g, a0);
    edge_accum(rb1, pb1, M0, M1, M2, M3, g, a1);

    float S0 = reduce_split(a0, g);
    float S1 = reduce_split(a1, g);

    const int c = ((g & 1) << 1) | ((g >> 1) & 1);   // class owned by lane g (<4)
    if (g < 4) {
        if (v0) out[4 * e0 + c] = fmaxf(S0, 0.f);
        if (v1) out[4 * e1 + c] = fmaxf(S1, 0.f);
    }
}

extern "C" void kernel_launch(void* const* d_in, const int* in_sizes, int n_in,
                              void* d_out, int out_size) {
    const float* rna  = (const float*)d_in[0];   // [20000,128] f32
    const float* prot = (const float*)d_in[1];   // [5000,128]  f32
    const int*   ridx = (const int*)d_in[2];     // [E] int32
    const int*   pidx = (const int*)d_in[3];     // [E] int32
    const float* wrel = (const float*)d_in[4];   // [4,128] f32
    const float* wcls = (const float*)d_in[5];   // [4,4]   f32
    float*       out  = (float*)d_out;           // [E,4]   f32

    const int E = in_sizes[2];

    fold_weights_kernel<<<1, NC * DIM>>>(wrel, wcls);

    const int threads = 256;
    const long long groups = ((long long)E + 1) / 2;           // 2 edges per group
    const long long total  = groups * LPE;
    const int blocks = (int)((total + threads - 1) / threads);
    edge_kernel<<<blocks, threads>>>(rna, prot, ridx, pidx, out, E);
}